// round 4
// baseline (speedup 1.0000x reference)
#include <cuda_runtime.h>
#include <cstdint>

#define NU   100000
#define NPC  20000
#define NURL 50000
#define EUP  250000
#define EUU  500000
#define HD   128
#define MAXB 128
#define XS   68      // Xs row stride in floats (64 rows + 4 pad; 272B, 16B-aligned, 4-way STS conflict max)
#define KC   32      // k-chunk staged per barrier

// ---------------- scratch ----------------
__device__ __align__(16) float g_user[NU*HD];
__device__ __align__(16) float g_pc_a[NPC*HD];
__device__ __align__(16) float g_pc_b[NPC*HD];
__device__ __align__(16) float g_url_a[NURL*HD];
__device__ __align__(16) float g_url_b[NURL*HD];
__device__ __align__(16) float g_mean_pc[NPC*HD];
__device__ __align__(16) float g_mean_url[NURL*HD];
__device__ __align__(16) float g_pcW[NPC*HD];
__device__ __align__(16) float g_urlW[NURL*HD];
__device__ __align__(16) float g_enr[NU*HD];

__device__ __align__(16) int g_cnt_upd[NPC];  __device__ int g_off_upd[NPC+1];  __device__ int g_cur_upd[NPC];  __device__ int g_adj_upd[EUP];
__device__ __align__(16) int g_cnt_uud[NURL]; __device__ int g_off_uud[NURL+1]; __device__ int g_cur_uud[NURL]; __device__ int g_adj_uud[EUU];
__device__ __align__(16) int g_cnt_ups[NU];   __device__ int g_off_ups[NU+1];   __device__ int g_cur_ups[NU];   __device__ int g_adj_ups[EUP];
__device__ __align__(16) int g_cnt_uus[NU];   __device__ int g_off_uus[NU+1];   __device__ int g_cur_uus[NU];   __device__ int g_adj_uus[EUU];
__device__ int g_part[4*MAXB];

// ---------------- f32x2 helpers ----------------
typedef unsigned long long u64;
__device__ __forceinline__ u64 f2fma(u64 a, u64 b, u64 c) {
    u64 d; asm("fma.rn.f32x2 %0, %1, %2, %3;" : "=l"(d) : "l"(a), "l"(b), "l"(c)); return d;
}
__device__ __forceinline__ void f2unpack(u64 v, float& x, float& y) {
    asm("mov.b64 {%0, %1}, %2;" : "=f"(x), "=f"(y) : "l"(v));
}

// ---------------- CSR build ----------------
__global__ void zero4_kernel(int* a, int na, int* b, int nb, int* c, int nc, int* d, int nd) {
    int i = blockIdx.x * blockDim.x + threadIdx.x;
    if (i < na) a[i] = 0;
    if (i < nb) b[i] = 0;
    if (i < nc) c[i] = 0;
    if (i < nd) d[i] = 0;
}

__global__ void count_kernel(const int* __restrict__ src, const int* __restrict__ dst, int E,
                             int* cntS, int* cntD) {
    int i = blockIdx.x * blockDim.x + threadIdx.x;
    if (i < E) {
        atomicAdd(&cntD[dst[i]], 1);
        atomicAdd(&cntS[src[i]], 1);
    }
}

struct SetDesc { const int* cnt; int* off; int* cur; int n; };

__device__ __forceinline__ SetDesc pick_set(int sel, SetDesc s0, SetDesc s1, SetDesc s2, SetDesc s3) {
    if (sel == 1) return s1;
    if (sel == 2) return s2;
    if (sel == 3) return s3;
    return s0;
}

__global__ void scanA_kernel(SetDesc s0, SetDesc s1, SetDesc s2, SetDesc s3) {
    SetDesc s = pick_set(blockIdx.y, s0, s1, s2, s3);
    int nb = (s.n + 1023) >> 10;
    if ((int)blockIdx.x >= nb) return;
    int tid = threadIdx.x;
    int i = blockIdx.x * 1024 + tid * 4;
    int sum = 0;
    #pragma unroll
    for (int j = 0; j < 4; j++) { int idx = i + j; if (idx < s.n) sum += s.cnt[idx]; }
    #pragma unroll
    for (int o = 16; o > 0; o >>= 1) sum += __shfl_down_sync(0xffffffffu, sum, o);
    __shared__ int ws[8];
    if ((tid & 31) == 0) ws[tid >> 5] = sum;
    __syncthreads();
    if (tid < 8) {
        int v = ws[tid];
        #pragma unroll
        for (int o = 4; o > 0; o >>= 1) v += __shfl_down_sync(0xffu, v, o);
        if (tid == 0) g_part[blockIdx.y * MAXB + blockIdx.x] = v;
    }
}

__global__ void scanB_kernel(SetDesc s0, SetDesc s1, SetDesc s2, SetDesc s3) {
    SetDesc s = pick_set(blockIdx.x, s0, s1, s2, s3);
    int nb = (s.n + 1023) >> 10;
    int tid = threadIdx.x;
    int v = (tid < nb) ? g_part[blockIdx.x * MAXB + tid] : 0;
    int lane = tid & 31, w = tid >> 5;
    int x = v;
    #pragma unroll
    for (int o = 1; o < 32; o <<= 1) { int y = __shfl_up_sync(0xffffffffu, x, o); if (lane >= o) x += y; }
    __shared__ int wt[4];
    if (lane == 31) wt[w] = x;
    __syncthreads();
    int add = 0;
    for (int j = 0; j < w; j++) add += wt[j];
    int incl = x + add;
    if (tid < nb) g_part[blockIdx.x * MAXB + tid] = incl - v;
    if (tid == 127) s.off[s.n] = incl;
}

__global__ void scanC_kernel(SetDesc s0, SetDesc s1, SetDesc s2, SetDesc s3) {
    SetDesc s = pick_set(blockIdx.y, s0, s1, s2, s3);
    int nb = (s.n + 1023) >> 10;
    if ((int)blockIdx.x >= nb) return;
    int tid = threadIdx.x;
    int base = g_part[blockIdx.y * MAXB + blockIdx.x];
    int i = blockIdx.x * 1024 + tid * 4;
    int v0 = 0, v1 = 0, v2 = 0, v3 = 0;
    if (i     < s.n) v0 = s.cnt[i];
    if (i + 1 < s.n) v1 = s.cnt[i + 1];
    if (i + 2 < s.n) v2 = s.cnt[i + 2];
    if (i + 3 < s.n) v3 = s.cnt[i + 3];
    int sv = v0 + v1 + v2 + v3;
    int lane = tid & 31, w = tid >> 5;
    int x = sv;
    #pragma unroll
    for (int o = 1; o < 32; o <<= 1) { int y = __shfl_up_sync(0xffffffffu, x, o); if (lane >= o) x += y; }
    __shared__ int wt[8];
    if (lane == 31) wt[w] = x;
    __syncthreads();
    int add = base;
    for (int j = 0; j < w; j++) add += wt[j];
    int e0 = add + x - sv;
    int e1 = e0 + v0, e2 = e1 + v1, e3 = e2 + v2;
    if (i     < s.n) { s.off[i]     = e0; s.cur[i]     = e0; }
    if (i + 1 < s.n) { s.off[i + 1] = e1; s.cur[i + 1] = e1; }
    if (i + 2 < s.n) { s.off[i + 2] = e2; s.cur[i + 2] = e2; }
    if (i + 3 < s.n) { s.off[i + 3] = e3; s.cur[i + 3] = e3; }
}

__global__ void fill_kernel(const int* __restrict__ src, const int* __restrict__ dst, int E,
                            int* curS, int* adjS, int* curD, int* adjD) {
    int i = blockIdx.x * blockDim.x + threadIdx.x;
    if (i < E) {
        int svv = src[i], dvv = dst[i];
        adjD[atomicAdd(&curD[dvv], 1)] = svv;
        adjS[atomicAdd(&curS[svv], 1)] = dvv;
    }
}

// ---------------- small-K input projection ----------------
__global__ void proj_kernel(const float* __restrict__ X, const float* __restrict__ W,
                            const float* __restrict__ b, float* __restrict__ out,
                            int N, int Kin) {
    __shared__ float sW[8 * HD];
    __shared__ float sb[HD];
    __shared__ float sx[32 * 8];
    int tid = threadIdx.x;
    for (int i = tid; i < Kin * HD; i += 128) sW[i] = W[i];
    sb[tid] = b[tid];
    int row0 = blockIdx.x * 32;
    int total = 32 * Kin;
    for (int i = tid; i < total; i += 128) {
        int gr = row0 + i / Kin;
        sx[i] = (gr < N) ? X[row0 * Kin + i] : 0.f;
    }
    __syncthreads();
    #pragma unroll 4
    for (int r = 0; r < 32; r++) {
        int gr = row0 + r;
        if (gr >= N) break;
        float acc = sb[tid];
        for (int j = 0; j < Kin; j++) acc = fmaf(sx[r * Kin + j], sW[j * HD + tid], acc);
        out[gr * HD + tid] = acc;
    }
}

// ---------------- gather-based segment mean ----------------
__global__ void agg_mean_kernel(const float* __restrict__ feat, const int* __restrict__ off,
                                const int* __restrict__ adj, float* __restrict__ out) {
    int s = blockIdx.x, t = threadIdx.x;
    int beg = off[s], end = off[s + 1];
    float acc = 0.f;
    int e = beg;
    for (; e + 4 <= end; e += 4) {
        int i0 = adj[e], i1 = adj[e + 1], i2 = adj[e + 2], i3 = adj[e + 3];
        float a0 = feat[i0 * HD + t], a1 = feat[i1 * HD + t];
        float a2 = feat[i2 * HD + t], a3 = feat[i3 * HD + t];
        acc += (a0 + a1) + (a2 + a3);
    }
    for (; e < end; e++) acc += feat[adj[e] * HD + t];
    float inv = (end > beg) ? 1.f / (float)(end - beg) : 0.f;
    out[s * HD + t] = acc * inv;
}

// ---------------- gemm_big: C[N,128] = relu?( [X1|X2] @ [W1;W2] + bias + resid ) ----------------
// 64 rows/block, 256 threads. X staged TRANSPOSED in smem (row-pairs -> packed f32x2 via LDS.128,
// no MOVs). W staged per 32-k chunk, pre-DUPLICATED (w,w) pairs (broadcast operand via LDS.128, no
// MOVs, no in-loop LDG). Inner loop per 2k: 2 X-LDS.128 + 8 W-LDS.128 + 32 f2fma -> fma-bound.
__global__ void __launch_bounds__(256) gemm_big(
    const float* __restrict__ X1, const float* __restrict__ X2,
    const float* __restrict__ W1, const float* __restrict__ W2,
    const float* __restrict__ bias, const float* __restrict__ resid,
    float* __restrict__ C, int N, int doRelu)
{
    extern __shared__ float smem[];
    const bool hasX2 = (X2 != nullptr);
    const int K = hasX2 ? 256 : 128;
    float* Xs = smem;                          // [K][XS]
    float4* Ws = (float4*)(smem + K * XS);     // [KC][4 j4][16 cq] of (w0,w0,w1,w1)

    const int tid = threadIdx.x;
    const int cq = tid & 15;          // 16 col groups
    const int rg = tid >> 4;          // 16 row groups of 4 rows
    const int r0 = rg * 4;
    const int row0 = blockIdx.x * 64;

    // ---- stage X transposed: Xs[k][r] ----
    {
        int nf4 = 64 * (K / 4);                 // float4 tiles
        int kmask = (K / 4) - 1;
        int kshift = hasX2 ? 6 : 5;
        for (int idx = tid; idx < nf4; idx += 256) {
            int k4 = idx & kmask;
            int r = idx >> kshift;
            int gr = row0 + r;
            int kk = k4 * 4;
            float4 v = make_float4(0.f, 0.f, 0.f, 0.f);
            if (gr < N) {
                if (kk < 128) v = *((const float4*)(X1 + gr * HD) + k4);
                else          v = *((const float4*)(X2 + gr * HD) + (k4 - 32));
            }
            Xs[(kk + 0) * XS + r] = v.x;
            Xs[(kk + 1) * XS + r] = v.y;
            Xs[(kk + 2) * XS + r] = v.z;
            Xs[(kk + 3) * XS + r] = v.w;
        }
    }

    u64 acc[2][8];
    #pragma unroll
    for (int p = 0; p < 2; p++)
        #pragma unroll
        for (int j = 0; j < 8; j++) acc[p][j] = 0ULL;

    const int nchunks = K / KC;
    for (int c = 0; c < nchunks; c++) {
        const int kb = c * KC;
        __syncthreads();   // prior chunk reads done (first iter: Xs staging done)
        // ---- stage W chunk, duplicated ----
        {
            int kl = tid >> 4;                       // 0..15
            #pragma unroll
            for (int s = 0; s < 2; s++) {
                int k = kl + s * 16;                 // local k in chunk
                int kg = kb + k;
                const float* Wrow = (kg < 128 || !hasX2) ? (W1 + kg * HD)
                                                         : (W2 + (kg - 128) * HD);
                #pragma unroll
                for (int j4 = 0; j4 < 4; j4++) {
                    float w0 = Wrow[cq + 32 * j4];
                    float w1 = Wrow[cq + 16 + 32 * j4];
                    Ws[(k * 4 + j4) * 16 + cq] = make_float4(w0, w0, w1, w1);
                }
            }
        }
        __syncthreads();
        // ---- compute 32 k ----
        #pragma unroll 4
        for (int kk = 0; kk < KC; kk += 2) {
            int kg = kb + kk;
            ulonglong2 xA = *(const ulonglong2*)&Xs[kg * XS + r0];
            ulonglong2 xB = *(const ulonglong2*)&Xs[(kg + 1) * XS + r0];
            #pragma unroll
            for (int j4 = 0; j4 < 4; j4++) {
                ulonglong2 wA = *(const ulonglong2*)&Ws[(kk * 4 + j4) * 16 + cq];
                ulonglong2 wB = *(const ulonglong2*)&Ws[((kk + 1) * 4 + j4) * 16 + cq];
                acc[0][2*j4]   = f2fma(xA.x, wA.x, acc[0][2*j4]);
                acc[1][2*j4]   = f2fma(xA.y, wA.x, acc[1][2*j4]);
                acc[0][2*j4+1] = f2fma(xA.x, wA.y, acc[0][2*j4+1]);
                acc[1][2*j4+1] = f2fma(xA.y, wA.y, acc[1][2*j4+1]);
                acc[0][2*j4]   = f2fma(xB.x, wB.x, acc[0][2*j4]);
                acc[1][2*j4]   = f2fma(xB.y, wB.x, acc[1][2*j4]);
                acc[0][2*j4+1] = f2fma(xB.x, wB.y, acc[0][2*j4+1]);
                acc[1][2*j4+1] = f2fma(xB.y, wB.y, acc[1][2*j4+1]);
            }
        }
    }

    // ---- epilogue: acc[p][jj] = rows (r0+2p, r0+2p+1), col cq+16*jj ----
    float ob[8];
    #pragma unroll
    for (int jj = 0; jj < 8; jj++) ob[jj] = bias ? bias[cq + 16 * jj] : 0.f;

    #pragma unroll
    for (int p = 0; p < 2; p++) {
        float v0[8], v1[8];
        #pragma unroll
        for (int jj = 0; jj < 8; jj++) f2unpack(acc[p][jj], v0[jj], v1[jj]);
        int gr0 = row0 + r0 + 2 * p;
        #pragma unroll
        for (int h = 0; h < 2; h++) {
            int gr = gr0 + h;
            if (gr >= N) continue;
            float* vv = h ? v1 : v0;
            #pragma unroll
            for (int jj = 0; jj < 8; jj++) {
                int col = cq + 16 * jj;
                float o = vv[jj] + ob[jj];
                if (resid) o += resid[gr * HD + col];
                if (doRelu) o = fmaxf(o, 0.f);
                C[gr * HD + col] = o;
            }
        }
    }
}

// ---------------- context gather ----------------
__global__ void ctx_gather_kernel(const float* __restrict__ pcW, const float* __restrict__ urlW,
                                  const int* __restrict__ offP, const int* __restrict__ adjP,
                                  const int* __restrict__ offR, const int* __restrict__ adjR,
                                  float* __restrict__ enr) {
    int u = blockIdx.x, t = threadIdx.x;
    float acc = enr[u * HD + t];
    {
        int beg = offP[u], end = offP[u + 1];
        int e = beg;
        for (; e + 4 <= end; e += 4) {
            int i0 = adjP[e], i1 = adjP[e+1], i2 = adjP[e+2], i3 = adjP[e+3];
            acc += (pcW[i0 * HD + t] + pcW[i1 * HD + t]) + (pcW[i2 * HD + t] + pcW[i3 * HD + t]);
        }
        for (; e < end; e++) acc += pcW[adjP[e] * HD + t];
    }
    {
        int beg = offR[u], end = offR[u + 1];
        int e = beg;
        for (; e + 4 <= end; e += 4) {
            int i0 = adjR[e], i1 = adjR[e+1], i2 = adjR[e+2], i3 = adjR[e+3];
            acc += (urlW[i0 * HD + t] + urlW[i1 * HD + t]) + (urlW[i2 * HD + t] + urlW[i3 * HD + t]);
        }
        for (; e < end; e++) acc += urlW[adjR[e] * HD + t];
    }
    enr[u * HD + t] = acc;
}

// ---------------- fused classifier ----------------
__global__ void __launch_bounds__(256) classifier_kernel(
    const float* __restrict__ enr, const float* __restrict__ Wc1, const float* __restrict__ bc1,
    const float* __restrict__ Wc2, const float* __restrict__ bc2,
    float* __restrict__ out, int N)
{
    __shared__ float sW1[HD * 64];
    __shared__ float sW2[64 * 2];
    __shared__ float sb1[64];
    __shared__ float sb2[2];
    __shared__ __align__(16) float se[8][HD];
    int tid = threadIdx.x;
    for (int i = tid; i < HD * 64; i += 256) sW1[i] = Wc1[i];
    for (int i = tid; i < 128; i += 256) sW2[i] = Wc2[i];
    if (tid < 64) sb1[tid] = bc1[tid];
    if (tid < 2) sb2[tid] = bc2[tid];
    __syncthreads();
    int warp = tid >> 5, lane = tid & 31;
    int row = blockIdx.x * 8 + warp;
    if (row < N) {
        float4 v = *((const float4*)enr + row * 32 + lane);
        ((float4*)&se[warp][0])[lane] = v;
    }
    __syncwarp();
    if (row < N) {
        float h0 = sb1[lane], h1 = sb1[lane + 32];
        #pragma unroll 8
        for (int k = 0; k < HD; k++) {
            float e = se[warp][k];
            h0 = fmaf(e, sW1[k * 64 + lane], h0);
            h1 = fmaf(e, sW1[k * 64 + lane + 32], h1);
        }
        h0 = fmaxf(h0, 0.f); h1 = fmaxf(h1, 0.f);
        float p0 = h0 * sW2[lane * 2 + 0] + h1 * sW2[(lane + 32) * 2 + 0];
        float p1 = h0 * sW2[lane * 2 + 1] + h1 * sW2[(lane + 32) * 2 + 1];
        #pragma unroll
        for (int o = 16; o > 0; o >>= 1) {
            p0 += __shfl_down_sync(0xffffffff, p0, o);
            p1 += __shfl_down_sync(0xffffffff, p1, o);
        }
        if (lane == 0) {
            out[row * 2 + 0] = p0 + sb2[0];
            out[row * 2 + 1] = p1 + sb2[1];
        }
    }
}

// ---------------- streams/events (static init) ----------------
struct StreamCtx {
    cudaStream_t s1, s2, s3;
    cudaEvent_t evRoot, evCSRup, evCSRuu, evUser, evPC, evURL, evS3;
    StreamCtx() {
        cudaStreamCreateWithFlags(&s1, cudaStreamNonBlocking);
        cudaStreamCreateWithFlags(&s2, cudaStreamNonBlocking);
        cudaStreamCreateWithFlags(&s3, cudaStreamNonBlocking);
        cudaEventCreateWithFlags(&evRoot,  cudaEventDisableTiming);
        cudaEventCreateWithFlags(&evCSRup, cudaEventDisableTiming);
        cudaEventCreateWithFlags(&evCSRuu, cudaEventDisableTiming);
        cudaEventCreateWithFlags(&evUser,  cudaEventDisableTiming);
        cudaEventCreateWithFlags(&evPC,    cudaEventDisableTiming);
        cudaEventCreateWithFlags(&evURL,   cudaEventDisableTiming);
        cudaEventCreateWithFlags(&evS3,    cudaEventDisableTiming);
    }
};
static StreamCtx g_sc;

// ---------------- host orchestration ----------------
#define SYMADDR(p, s) do { void* _t; cudaGetSymbolAddress(&_t, s); p = (decltype(p))_t; } while (0)

extern "C" void kernel_launch(void* const* d_in, const int* in_sizes, int n_in,
                              void* d_out, int out_size) {
    const float* x_user = (const float*)d_in[0];
    const float* x_pc   = (const float*)d_in[1];
    const float* x_url  = (const float*)d_in[2];
    const int* up_src   = (const int*)d_in[3];
    const int* up_dst   = (const int*)d_in[4];
    const int* uu_src   = (const int*)d_in[5];
    const int* uu_dst   = (const int*)d_in[6];
    const float* Wu = (const float*)d_in[7];
    const float* bu = (const float*)d_in[8];
    const float* Wp = (const float*)d_in[9];
    const float* bp = (const float*)d_in[10];
    const float* Wrf = (const float*)d_in[11];
    const float* brf = (const float*)d_in[12];
    const float* Wl_pc = (const float*)d_in[13];
    const float* bl_pc = (const float*)d_in[14];
    const float* Wr_pc = (const float*)d_in[15];
    const float* Wl_url = (const float*)d_in[16];
    const float* bl_url = (const float*)d_in[17];
    const float* Wr_url = (const float*)d_in[18];
    const float* Wctx = (const float*)d_in[19];
    const float* bctx = (const float*)d_in[20];
    const float* Wc1 = (const float*)d_in[21];
    const float* bc1 = (const float*)d_in[22];
    const float* Wc2 = (const float*)d_in[23];
    const float* bc2 = (const float*)d_in[24];
    float* out = (float*)d_out;

    float *user, *pc_a, *pc_b, *url_a, *url_b, *mean_pc, *mean_url, *pcW, *urlW, *enr;
    SYMADDR(user, g_user); SYMADDR(pc_a, g_pc_a); SYMADDR(pc_b, g_pc_b);
    SYMADDR(url_a, g_url_a); SYMADDR(url_b, g_url_b);
    SYMADDR(mean_pc, g_mean_pc); SYMADDR(mean_url, g_mean_url);
    SYMADDR(pcW, g_pcW); SYMADDR(urlW, g_urlW); SYMADDR(enr, g_enr);

    int *cnt_upd, *off_upd, *cur_upd, *adj_upd;
    int *cnt_uud, *off_uud, *cur_uud, *adj_uud;
    int *cnt_ups, *off_ups, *cur_ups, *adj_ups;
    int *cnt_uus, *off_uus, *cur_uus, *adj_uus;
    SYMADDR(cnt_upd, g_cnt_upd); SYMADDR(off_upd, g_off_upd); SYMADDR(cur_upd, g_cur_upd); SYMADDR(adj_upd, g_adj_upd);
    SYMADDR(cnt_uud, g_cnt_uud); SYMADDR(off_uud, g_off_uud); SYMADDR(cur_uud, g_cur_uud); SYMADDR(adj_uud, g_adj_uud);
    SYMADDR(cnt_ups, g_cnt_ups); SYMADDR(off_ups, g_off_ups); SYMADDR(cur_ups, g_cur_ups); SYMADDR(adj_ups, g_adj_ups);
    SYMADDR(cnt_uus, g_cnt_uus); SYMADDR(off_uus, g_off_uus); SYMADDR(cur_uus, g_cur_uus); SYMADDR(adj_uus, g_adj_uus);

    const int SMK256 = 256 * XS * 4 + KC * 4 * 16 * 16;   // Xs + Ws4
    const int SMK128 = 128 * XS * 4 + KC * 4 * 16 * 16;
    cudaFuncSetAttribute(gemm_big, cudaFuncAttributeMaxDynamicSharedMemorySize, SMK256);

    cudaStream_t s0 = 0;
    cudaStream_t s1 = g_sc.s1, s2 = g_sc.s2, s3 = g_sc.s3;

    // ---- fork ----
    cudaEventRecord(g_sc.evRoot, s0);
    cudaStreamWaitEvent(s1, g_sc.evRoot, 0);
    cudaStreamWaitEvent(s2, g_sc.evRoot, 0);
    cudaStreamWaitEvent(s3, g_sc.evRoot, 0);

    // ---- s3: user projection, then enr GEMM ----
    proj_kernel<<<(NU + 31) / 32, 128, 0, s3>>>(x_user, Wu, bu, user, NU, 6);
    cudaEventRecord(g_sc.evUser, s3);
    gemm_big<<<(NU + 63) / 64, 256, SMK128, s3>>>(user, nullptr, Wctx, nullptr, bctx, nullptr, enr, NU, 0);
    cudaEventRecord(g_sc.evS3, s3);

    // ---- s1/s2: pc/url input projections ----
    proj_kernel<<<(NPC + 31) / 32, 128, 0, s1>>>(x_pc, Wp, bp, pc_a, NPC, 4);
    proj_kernel<<<(NURL + 31) / 32, 128, 0, s2>>>(x_url, Wrf, brf, url_a, NURL, 3);

    // ---- s0: CSR build ----
    zero4_kernel<<<(NU + 255) / 256, 256, 0, s0>>>(cnt_upd, NPC, cnt_uud, NURL, cnt_ups, NU, cnt_uus, NU);
    count_kernel<<<(EUP + 255) / 256, 256, 0, s0>>>(up_src, up_dst, EUP, cnt_ups, cnt_upd);
    count_kernel<<<(EUU + 255) / 256, 256, 0, s0>>>(uu_src, uu_dst, EUU, cnt_uus, cnt_uud);
    SetDesc d0{cnt_upd, off_upd, cur_upd, NPC};
    SetDesc d1{cnt_uud, off_uud, cur_uud, NURL};
    SetDesc d2{cnt_ups, off_ups, cur_ups, NU};
    SetDesc d3{cnt_uus, off_uus, cur_uus, NU};
    dim3 gScan((NU + 1023) / 1024, 4);
    scanA_kernel<<<gScan, 256, 0, s0>>>(d0, d1, d2, d3);
    scanB_kernel<<<4, 128, 0, s0>>>(d0, d1, d2, d3);
    scanC_kernel<<<gScan, 256, 0, s0>>>(d0, d1, d2, d3);
    fill_kernel<<<(EUP + 255) / 256, 256, 0, s0>>>(up_src, up_dst, EUP, cur_ups, adj_ups, cur_upd, adj_upd);
    cudaEventRecord(g_sc.evCSRup, s0);
    fill_kernel<<<(EUU + 255) / 256, 256, 0, s0>>>(uu_src, uu_dst, EUU, cur_uus, adj_uus, cur_uud, adj_uud);
    cudaEventRecord(g_sc.evCSRuu, s0);

    // ---- s1: pc chain ----
    cudaStreamWaitEvent(s1, g_sc.evCSRup, 0);
    cudaStreamWaitEvent(s1, g_sc.evUser, 0);
    agg_mean_kernel<<<NPC, 128, 0, s1>>>(user, off_upd, adj_upd, mean_pc);
    gemm_big<<<(NPC + 63) / 64, 256, SMK256, s1>>>(mean_pc, pc_a, Wl_pc, Wr_pc, bl_pc, nullptr, pc_b, NPC, 1);
    gemm_big<<<(NPC + 63) / 64, 256, SMK256, s1>>>(mean_pc, pc_b, Wl_pc + HD * HD, Wr_pc + HD * HD,
                                                   bl_pc + HD, pc_b, pc_a, NPC, 1);
    gemm_big<<<(NPC + 63) / 64, 256, SMK128, s1>>>(pc_a, nullptr, Wctx + HD * HD, nullptr, nullptr, nullptr, pcW, NPC, 0);
    cudaEventRecord(g_sc.evPC, s1);

    // ---- s2: url chain ----
    cudaStreamWaitEvent(s2, g_sc.evCSRuu, 0);
    cudaStreamWaitEvent(s2, g_sc.evUser, 0);
    agg_mean_kernel<<<NURL, 128, 0, s2>>>(user, off_uud, adj_uud, mean_url);
    gemm_big<<<(NURL + 63) / 64, 256, SMK256, s2>>>(mean_url, url_a, Wl_url, Wr_url, bl_url, nullptr, url_b, NURL, 1);
    gemm_big<<<(NURL + 63) / 64, 256, SMK256, s2>>>(mean_url, url_b, Wl_url + HD * HD, Wr_url + HD * HD,
                                                    bl_url + HD, url_b, url_a, NURL, 1);
    gemm_big<<<(NURL + 63) / 64, 256, SMK128, s2>>>(url_a, nullptr, Wctx + 2 * HD * HD, nullptr, nullptr, nullptr, urlW, NURL, 0);
    cudaEventRecord(g_sc.evURL, s2);

    // ---- join on s0: context gather + classifier ----
    cudaStreamWaitEvent(s0, g_sc.evPC, 0);
    cudaStreamWaitEvent(s0, g_sc.evURL, 0);
    cudaStreamWaitEvent(s0, g_sc.evS3, 0);
    ctx_gather_kernel<<<NU, 128, 0, s0>>>(pcW, urlW, off_ups, adj_ups, off_uus, adj_uus, enr);
    classifier_kernel<<<(NU + 7) / 8, 256, 0, s0>>>(enr, Wc1, bc1, Wc2, bc2, out, NU);
}

// round 5
// speedup vs baseline: 1.7287x; 1.7287x over previous
#include <cuda_runtime.h>
#include <cstdint>

#define NU   100000
#define NPC  20000
#define NURL 50000
#define EUP  250000
#define EUU  500000
#define HD   128
#define MAXB 128

// ---------------- scratch ----------------
__device__ __align__(16) float g_user[NU*HD];
__device__ __align__(16) float g_pc_a[NPC*HD];
__device__ __align__(16) float g_pc_b[NPC*HD];
__device__ __align__(16) float g_url_a[NURL*HD];
__device__ __align__(16) float g_url_b[NURL*HD];
__device__ __align__(16) float g_mean_pc[NPC*HD];
__device__ __align__(16) float g_mean_url[NURL*HD];
__device__ __align__(16) float g_pcH[NPC*64];
__device__ __align__(16) float g_urlH[NURL*64];
__device__ __align__(16) float g_userH[NU*64];
__device__ __align__(16) float g_Wf[3*HD*64];     // WfU | WfP | WfR
__device__ __align__(16) float g_bH[64];

__device__ __align__(16) int g_cnt_upd[NPC];  __device__ int g_off_upd[NPC+1];  __device__ int g_cur_upd[NPC];  __device__ int g_adj_upd[EUP];
__device__ __align__(16) int g_cnt_uud[NURL]; __device__ int g_off_uud[NURL+1]; __device__ int g_cur_uud[NURL]; __device__ int g_adj_uud[EUU];
__device__ __align__(16) int g_cnt_ups[NU];   __device__ int g_off_ups[NU+1];   __device__ int g_cur_ups[NU];   __device__ int g_adj_ups[EUP];
__device__ __align__(16) int g_cnt_uus[NU];   __device__ int g_off_uus[NU+1];   __device__ int g_cur_uus[NU];   __device__ int g_adj_uus[EUU];
__device__ int g_part[4*MAXB];

// ---------------- f32x2 helpers ----------------
typedef unsigned long long u64;
__device__ __forceinline__ u64 f2fma(u64 a, u64 b, u64 c) {
    u64 d; asm("fma.rn.f32x2 %0, %1, %2, %3;" : "=l"(d) : "l"(a), "l"(b), "l"(c)); return d;
}
__device__ __forceinline__ u64 f2pack(float x) {
    u64 r; asm("mov.b64 %0, {%1, %1};" : "=l"(r) : "f"(x)); return r;
}
__device__ __forceinline__ void f2unpack(u64 v, float& x, float& y) {
    asm("mov.b64 {%0, %1}, %2;" : "=f"(x), "=f"(y) : "l"(v));
}

// ---------------- CSR build ----------------
__global__ void zero4_kernel(int* a, int na, int* b, int nb, int* c, int nc, int* d, int nd) {
    int i = blockIdx.x * blockDim.x + threadIdx.x;
    if (i < na) a[i] = 0;
    if (i < nb) b[i] = 0;
    if (i < nc) c[i] = 0;
    if (i < nd) d[i] = 0;
}

__global__ void count_kernel(const int* __restrict__ src, const int* __restrict__ dst, int E,
                             int* cntS, int* cntD) {
    int i = blockIdx.x * blockDim.x + threadIdx.x;
    if (i < E) {
        atomicAdd(&cntD[dst[i]], 1);
        atomicAdd(&cntS[src[i]], 1);
    }
}

struct SetDesc { const int* cnt; int* off; int* cur; int n; };

__device__ __forceinline__ SetDesc pick_set(int sel, SetDesc s0, SetDesc s1, SetDesc s2, SetDesc s3) {
    if (sel == 1) return s1;
    if (sel == 2) return s2;
    if (sel == 3) return s3;
    return s0;
}

__global__ void scanA_kernel(SetDesc s0, SetDesc s1, SetDesc s2, SetDesc s3) {
    SetDesc s = pick_set(blockIdx.y, s0, s1, s2, s3);
    int nb = (s.n + 1023) >> 10;
    if ((int)blockIdx.x >= nb) return;
    int tid = threadIdx.x;
    int i = blockIdx.x * 1024 + tid * 4;
    int sum = 0;
    #pragma unroll
    for (int j = 0; j < 4; j++) { int idx = i + j; if (idx < s.n) sum += s.cnt[idx]; }
    #pragma unroll
    for (int o = 16; o > 0; o >>= 1) sum += __shfl_down_sync(0xffffffffu, sum, o);
    __shared__ int ws[8];
    if ((tid & 31) == 0) ws[tid >> 5] = sum;
    __syncthreads();
    if (tid < 8) {
        int v = ws[tid];
        #pragma unroll
        for (int o = 4; o > 0; o >>= 1) v += __shfl_down_sync(0xffu, v, o);
        if (tid == 0) g_part[blockIdx.y * MAXB + blockIdx.x] = v;
    }
}

__global__ void scanB_kernel(SetDesc s0, SetDesc s1, SetDesc s2, SetDesc s3) {
    SetDesc s = pick_set(blockIdx.x, s0, s1, s2, s3);
    int nb = (s.n + 1023) >> 10;
    int tid = threadIdx.x;
    int v = (tid < nb) ? g_part[blockIdx.x * MAXB + tid] : 0;
    int lane = tid & 31, w = tid >> 5;
    int x = v;
    #pragma unroll
    for (int o = 1; o < 32; o <<= 1) { int y = __shfl_up_sync(0xffffffffu, x, o); if (lane >= o) x += y; }
    __shared__ int wt[4];
    if (lane == 31) wt[w] = x;
    __syncthreads();
    int add = 0;
    for (int j = 0; j < w; j++) add += wt[j];
    int incl = x + add;
    if (tid < nb) g_part[blockIdx.x * MAXB + tid] = incl - v;
    if (tid == 127) s.off[s.n] = incl;
}

__global__ void scanC_kernel(SetDesc s0, SetDesc s1, SetDesc s2, SetDesc s3) {
    SetDesc s = pick_set(blockIdx.y, s0, s1, s2, s3);
    int nb = (s.n + 1023) >> 10;
    if ((int)blockIdx.x >= nb) return;
    int tid = threadIdx.x;
    int base = g_part[blockIdx.y * MAXB + blockIdx.x];
    int i = blockIdx.x * 1024 + tid * 4;
    int v0 = 0, v1 = 0, v2 = 0, v3 = 0;
    if (i     < s.n) v0 = s.cnt[i];
    if (i + 1 < s.n) v1 = s.cnt[i + 1];
    if (i + 2 < s.n) v2 = s.cnt[i + 2];
    if (i + 3 < s.n) v3 = s.cnt[i + 3];
    int sv = v0 + v1 + v2 + v3;
    int lane = tid & 31, w = tid >> 5;
    int x = sv;
    #pragma unroll
    for (int o = 1; o < 32; o <<= 1) { int y = __shfl_up_sync(0xffffffffu, x, o); if (lane >= o) x += y; }
    __shared__ int wt[8];
    if (lane == 31) wt[w] = x;
    __syncthreads();
    int add = base;
    for (int j = 0; j < w; j++) add += wt[j];
    int e0 = add + x - sv;
    int e1 = e0 + v0, e2 = e1 + v1, e3 = e2 + v2;
    if (i     < s.n) { s.off[i]     = e0; s.cur[i]     = e0; }
    if (i + 1 < s.n) { s.off[i + 1] = e1; s.cur[i + 1] = e1; }
    if (i + 2 < s.n) { s.off[i + 2] = e2; s.cur[i + 2] = e2; }
    if (i + 3 < s.n) { s.off[i + 3] = e3; s.cur[i + 3] = e3; }
}

__global__ void fill_kernel(const int* __restrict__ src, const int* __restrict__ dst, int E,
                            int* curS, int* adjS, int* curD, int* adjD) {
    int i = blockIdx.x * blockDim.x + threadIdx.x;
    if (i < E) {
        int svv = src[i], dvv = dst[i];
        adjD[atomicAdd(&curD[dvv], 1)] = svv;
        adjS[atomicAdd(&curS[svv], 1)] = dvv;
    }
}

// ---------------- small-K input projection ----------------
__global__ void proj_kernel(const float* __restrict__ X, const float* __restrict__ W,
                            const float* __restrict__ b, float* __restrict__ out,
                            int N, int Kin) {
    __shared__ float sW[8 * HD];
    __shared__ float sb[HD];
    __shared__ float sx[32 * 8];
    int tid = threadIdx.x;
    for (int i = tid; i < Kin * HD; i += 128) sW[i] = W[i];
    sb[tid] = b[tid];
    int row0 = blockIdx.x * 32;
    int total = 32 * Kin;
    for (int i = tid; i < total; i += 128) {
        int gr = row0 + i / Kin;
        sx[i] = (gr < N) ? X[row0 * Kin + i] : 0.f;
    }
    __syncthreads();
    #pragma unroll 4
    for (int r = 0; r < 32; r++) {
        int gr = row0 + r;
        if (gr >= N) break;
        float acc = sb[tid];
        for (int j = 0; j < Kin; j++) acc = fmaf(sx[r * Kin + j], sW[j * HD + tid], acc);
        out[gr * HD + tid] = acc;
    }
}

// ---------------- weight folding: Wf[seg] = Wctx[seg*128:,:128] @ Wc1 ; bH = bctx@Wc1 + bc1 ----------------
__global__ void fuse_w_kernel(const float* __restrict__ Wctx, const float* __restrict__ bctx,
                              const float* __restrict__ Wc1, const float* __restrict__ bc1,
                              float* __restrict__ Wf, float* __restrict__ bH) {
    int b = blockIdx.x;
    if (b == 96) {      // bias block: 64 threads
        int c = threadIdx.x;
        if (c < 64) {
            float acc = bc1[c];
            for (int m = 0; m < HD; m++) acc = fmaf(bctx[m], Wc1[m * 64 + c], acc);
            bH[c] = acc;
        }
        return;
    }
    __shared__ float sWc1[HD * 64];
    int tid = threadIdx.x;                       // 256 threads
    for (int i = tid; i < HD * 64; i += 256) sWc1[i] = Wc1[i];
    __syncthreads();
    int seg = b >> 5;                            // 0..2
    int r = (b & 31) * 4 + (tid >> 6);           // row within 128
    int c = tid & 63;
    int j = seg * HD + r;                        // row in Wctx [384][128]
    float acc = 0.f;
    #pragma unroll 8
    for (int m = 0; m < HD; m++) acc = fmaf(Wctx[j * HD + m], sWc1[m * 64 + c], acc);
    Wf[(seg * HD + r) * 64 + c] = acc;
}

// ---------------- gather-based segment mean ----------------
__global__ void agg_mean_kernel(const float* __restrict__ feat, const int* __restrict__ off,
                                const int* __restrict__ adj, float* __restrict__ out) {
    int s = blockIdx.x, t = threadIdx.x;
    int beg = off[s], end = off[s + 1];
    float acc = 0.f;
    int e = beg;
    for (; e + 4 <= end; e += 4) {
        int i0 = adj[e], i1 = adj[e + 1], i2 = adj[e + 2], i3 = adj[e + 3];
        float a0 = feat[i0 * HD + t], a1 = feat[i1 * HD + t];
        float a2 = feat[i2 * HD + t], a3 = feat[i3 * HD + t];
        acc += (a0 + a1) + (a2 + a3);
    }
    for (; e < end; e++) acc += feat[adj[e] * HD + t];
    float inv = (end > beg) ? 1.f / (float)(end - beg) : 0.f;
    out[s * HD + t] = acc * inv;
}

// ---------------- fused GEMM (R3 version): C = act(A@W1 [+ B@W2] [+bias] [+resid]), 128 cols ----------------
#define ASTRIDE 132
__global__ void __launch_bounds__(256, 2) gemm128(
    const float* __restrict__ A, const float* __restrict__ W1,
    const float* __restrict__ B, const float* __restrict__ W2,
    const float* __restrict__ bias, const float* __restrict__ resid,
    float* __restrict__ C, int N, int doRelu)
{
    extern __shared__ float smem[];
    float* As = smem;
    float* Bs = smem + 64 * ASTRIDE;
    const int tid = threadIdx.x;
    const int row0 = blockIdx.x * 64;
    const bool hasB = (B != nullptr);

    #pragma unroll
    for (int i = 0; i < 8; i++) {
        int slot = i * 256 + tid;
        int r = slot >> 5;
        int c4 = slot & 31;
        int gr = row0 + r;
        float4 va = make_float4(0.f, 0.f, 0.f, 0.f);
        if (gr < N) va = *((const float4*)A + gr * 32 + c4);
        *(float4*)(As + r * ASTRIDE + c4 * 4) = va;
        if (hasB) {
            float4 vb = make_float4(0.f, 0.f, 0.f, 0.f);
            if (gr < N) vb = *((const float4*)B + gr * 32 + c4);
            *(float4*)(Bs + r * ASTRIDE + c4 * 4) = vb;
        }
    }
    __syncthreads();

    const int cq = tid & 15;
    const int rg = tid >> 4;
    const ulonglong2* W1v = (const ulonglong2*)W1;
    const ulonglong2* W2v = (const ulonglong2*)W2;

    u64 acc[4][4];
    #pragma unroll
    for (int i = 0; i < 4; i++)
        #pragma unroll
        for (int p = 0; p < 4; p++) acc[i][p] = 0ULL;

    if (hasB) {
        #pragma unroll 1
        for (int k = 0; k < 128; k += 2) {
            ulonglong2 w10a = W1v[k * 32 + cq * 2];
            ulonglong2 w10b = W1v[k * 32 + cq * 2 + 1];
            ulonglong2 w11a = W1v[(k + 1) * 32 + cq * 2];
            ulonglong2 w11b = W1v[(k + 1) * 32 + cq * 2 + 1];
            ulonglong2 w20a = W2v[k * 32 + cq * 2];
            ulonglong2 w20b = W2v[k * 32 + cq * 2 + 1];
            ulonglong2 w21a = W2v[(k + 1) * 32 + cq * 2];
            ulonglong2 w21b = W2v[(k + 1) * 32 + cq * 2 + 1];
            #pragma unroll
            for (int i = 0; i < 4; i++) {
                float2 a2 = *(const float2*)&As[(rg + i * 16) * ASTRIDE + k];
                u64 aa0 = f2pack(a2.x), aa1 = f2pack(a2.y);
                acc[i][0] = f2fma(aa0, w10a.x, acc[i][0]);
                acc[i][1] = f2fma(aa0, w10a.y, acc[i][1]);
                acc[i][2] = f2fma(aa0, w10b.x, acc[i][2]);
                acc[i][3] = f2fma(aa0, w10b.y, acc[i][3]);
                acc[i][0] = f2fma(aa1, w11a.x, acc[i][0]);
                acc[i][1] = f2fma(aa1, w11a.y, acc[i][1]);
                acc[i][2] = f2fma(aa1, w11b.x, acc[i][2]);
                acc[i][3] = f2fma(aa1, w11b.y, acc[i][3]);
                float2 b2 = *(const float2*)&Bs[(rg + i * 16) * ASTRIDE + k];
                u64 bb0 = f2pack(b2.x), bb1 = f2pack(b2.y);
                acc[i][0] = f2fma(bb0, w20a.x, acc[i][0]);
                acc[i][1] = f2fma(bb0, w20a.y, acc[i][1]);
                acc[i][2] = f2fma(bb0, w20b.x, acc[i][2]);
                acc[i][3] = f2fma(bb0, w20b.y, acc[i][3]);
                acc[i][0] = f2fma(bb1, w21a.x, acc[i][0]);
                acc[i][1] = f2fma(bb1, w21a.y, acc[i][1]);
                acc[i][2] = f2fma(bb1, w21b.x, acc[i][2]);
                acc[i][3] = f2fma(bb1, w21b.y, acc[i][3]);
            }
        }
    } else {
        #pragma unroll 1
        for (int k = 0; k < 128; k += 2) {
            ulonglong2 w10a = W1v[k * 32 + cq * 2];
            ulonglong2 w10b = W1v[k * 32 + cq * 2 + 1];
            ulonglong2 w11a = W1v[(k + 1) * 32 + cq * 2];
            ulonglong2 w11b = W1v[(k + 1) * 32 + cq * 2 + 1];
            #pragma unroll
            for (int i = 0; i < 4; i++) {
                float2 a2 = *(const float2*)&As[(rg + i * 16) * ASTRIDE + k];
                u64 aa0 = f2pack(a2.x), aa1 = f2pack(a2.y);
                acc[i][0] = f2fma(aa0, w10a.x, acc[i][0]);
                acc[i][1] = f2fma(aa0, w10a.y, acc[i][1]);
                acc[i][2] = f2fma(aa0, w10b.x, acc[i][2]);
                acc[i][3] = f2fma(aa0, w10b.y, acc[i][3]);
                acc[i][0] = f2fma(aa1, w11a.x, acc[i][0]);
                acc[i][1] = f2fma(aa1, w11a.y, acc[i][1]);
                acc[i][2] = f2fma(aa1, w11b.x, acc[i][2]);
                acc[i][3] = f2fma(aa1, w11b.y, acc[i][3]);
            }
        }
    }

    const int c0 = cq * 8;
    float ob[8] = {0,0,0,0,0,0,0,0};
    if (bias) {
        float4 b0 = *((const float4*)(bias + c0));
        float4 b1 = *((const float4*)(bias + c0 + 4));
        ob[0]=b0.x; ob[1]=b0.y; ob[2]=b0.z; ob[3]=b0.w;
        ob[4]=b1.x; ob[5]=b1.y; ob[6]=b1.z; ob[7]=b1.w;
    }
    #pragma unroll
    for (int i = 0; i < 4; i++) {
        int gr = row0 + rg + i * 16;
        if (gr >= N) continue;
        float o[8];
        f2unpack(acc[i][0], o[0], o[1]);
        f2unpack(acc[i][1], o[2], o[3]);
        f2unpack(acc[i][2], o[4], o[5]);
        f2unpack(acc[i][3], o[6], o[7]);
        #pragma unroll
        for (int j = 0; j < 8; j++) o[j] += ob[j];
        if (resid) {
            float4 r0 = *((const float4*)(resid + gr * HD + c0));
            float4 r1 = *((const float4*)(resid + gr * HD + c0 + 4));
            o[0]+=r0.x; o[1]+=r0.y; o[2]+=r0.z; o[3]+=r0.w;
            o[4]+=r1.x; o[5]+=r1.y; o[6]+=r1.z; o[7]+=r1.w;
        }
        if (doRelu) {
            #pragma unroll
            for (int j = 0; j < 8; j++) o[j] = fmaxf(o[j], 0.f);
        }
        *(float4*)(C + gr * HD + c0)     = make_float4(o[0], o[1], o[2], o[3]);
        *(float4*)(C + gr * HD + c0 + 4) = make_float4(o[4], o[5], o[6], o[7]);
    }
}

// ---------------- gemm64: C[N,64] = X[N,128] @ Wf[128,64] (+bias) ----------------
__global__ void __launch_bounds__(256) gemm64(
    const float* __restrict__ X, const float* __restrict__ Wf,
    const float* __restrict__ bias, float* __restrict__ C, int N)
{
    extern __shared__ float smem[];
    float* As = smem;
    const int tid = threadIdx.x;
    const int row0 = blockIdx.x * 64;

    #pragma unroll
    for (int i = 0; i < 8; i++) {
        int slot = i * 256 + tid;
        int r = slot >> 5;
        int c4 = slot & 31;
        int gr = row0 + r;
        float4 va = make_float4(0.f, 0.f, 0.f, 0.f);
        if (gr < N) va = *((const float4*)X + gr * 32 + c4);
        *(float4*)(As + r * ASTRIDE + c4 * 4) = va;
    }
    __syncthreads();

    const int cq = tid & 15;          // 16 col groups of 4 cols
    const int rg = tid >> 4;          // rows rg + 16*i
    const ulonglong2* Wv = (const ulonglong2*)Wf;   // [k][16]

    u64 acc[4][2];
    #pragma unroll
    for (int i = 0; i < 4; i++) { acc[i][0] = 0ULL; acc[i][1] = 0ULL; }

    #pragma unroll 2
    for (int k = 0; k < 128; k += 2) {
        ulonglong2 wA = Wv[k * 16 + cq];
        ulonglong2 wB = Wv[(k + 1) * 16 + cq];
        #pragma unroll
        for (int i = 0; i < 4; i++) {
            float2 a2 = *(const float2*)&As[(rg + i * 16) * ASTRIDE + k];
            u64 aa0 = f2pack(a2.x), aa1 = f2pack(a2.y);
            acc[i][0] = f2fma(aa0, wA.x, acc[i][0]);
            acc[i][1] = f2fma(aa0, wA.y, acc[i][1]);
            acc[i][0] = f2fma(aa1, wB.x, acc[i][0]);
            acc[i][1] = f2fma(aa1, wB.y, acc[i][1]);
        }
    }

    const int c0 = cq * 4;
    float ob[4] = {0, 0, 0, 0};
    if (bias) {
        float4 bv = *((const float4*)(bias + c0));
        ob[0] = bv.x; ob[1] = bv.y; ob[2] = bv.z; ob[3] = bv.w;
    }
    #pragma unroll
    for (int i = 0; i < 4; i++) {
        int gr = row0 + rg + i * 16;
        if (gr >= N) continue;
        float o[4];
        f2unpack(acc[i][0], o[0], o[1]);
        f2unpack(acc[i][1], o[2], o[3]);
        *(float4*)(C + gr * 64 + c0) = make_float4(o[0] + ob[0], o[1] + ob[1], o[2] + ob[2], o[3] + ob[3]);
    }
}

// ---------------- fused gather + classifier ----------------
// out[u] = relu(userH[u] + sum_pc pcH[dst] + sum_url urlH[dst]) @ Wc2 + bc2
__global__ void gather_cls_kernel(const float* __restrict__ userH,
                                  const float* __restrict__ pcH, const float* __restrict__ urlH,
                                  const int* __restrict__ offP, const int* __restrict__ adjP,
                                  const int* __restrict__ offR, const int* __restrict__ adjR,
                                  const float* __restrict__ Wc2, const float* __restrict__ bc2,
                                  float* __restrict__ out, int N)
{
    __shared__ float sW2[128];
    __shared__ float red[4][2];
    int tid = threadIdx.x;                    // 128 threads = 2 users x 64
    sW2[tid] = Wc2[tid];
    int u = blockIdx.x * 2 + (tid >> 6);
    int t = tid & 63;
    float acc = 0.f;
    if (u < N) {
        acc = userH[u * 64 + t];
        {
            int e = offP[u], end = offP[u + 1];
            for (; e + 4 <= end; e += 4) {
                int i0 = adjP[e], i1 = adjP[e+1], i2 = adjP[e+2], i3 = adjP[e+3];
                acc += (pcH[i0 * 64 + t] + pcH[i1 * 64 + t]) + (pcH[i2 * 64 + t] + pcH[i3 * 64 + t]);
            }
            for (; e < end; e++) acc += pcH[adjP[e] * 64 + t];
        }
        {
            int e = offR[u], end = offR[u + 1];
            for (; e + 4 <= end; e += 4) {
                int i0 = adjR[e], i1 = adjR[e+1], i2 = adjR[e+2], i3 = adjR[e+3];
                acc += (urlH[i0 * 64 + t] + urlH[i1 * 64 + t]) + (urlH[i2 * 64 + t] + urlH[i3 * 64 + t]);
            }
            for (; e < end; e++) acc += urlH[adjR[e] * 64 + t];
        }
    }
    __syncthreads();   // sW2 ready
    float h = fmaxf(acc, 0.f);
    float p0 = h * sW2[t * 2 + 0];
    float p1 = h * sW2[t * 2 + 1];
    #pragma unroll
    for (int o = 16; o > 0; o >>= 1) {
        p0 += __shfl_down_sync(0xffffffffu, p0, o);
        p1 += __shfl_down_sync(0xffffffffu, p1, o);
    }
    int w = tid >> 5;
    if ((tid & 31) == 0) { red[w][0] = p0; red[w][1] = p1; }
    __syncthreads();
    if (tid < 4) {
        int ul = tid >> 1, c = tid & 1;
        int uu = blockIdx.x * 2 + ul;
        if (uu < N) out[uu * 2 + c] = red[ul * 2][c] + red[ul * 2 + 1][c] + bc2[c];
    }
}

// ---------------- streams/events (static init) ----------------
struct StreamCtx {
    cudaStream_t s1, s2, s3;
    cudaEvent_t evRoot, evCSRup, evCSRuu, evUser, evPC, evURL, evS3, evFW;
    StreamCtx() {
        cudaStreamCreateWithFlags(&s1, cudaStreamNonBlocking);
        cudaStreamCreateWithFlags(&s2, cudaStreamNonBlocking);
        cudaStreamCreateWithFlags(&s3, cudaStreamNonBlocking);
        cudaEventCreateWithFlags(&evRoot,  cudaEventDisableTiming);
        cudaEventCreateWithFlags(&evCSRup, cudaEventDisableTiming);
        cudaEventCreateWithFlags(&evCSRuu, cudaEventDisableTiming);
        cudaEventCreateWithFlags(&evUser,  cudaEventDisableTiming);
        cudaEventCreateWithFlags(&evPC,    cudaEventDisableTiming);
        cudaEventCreateWithFlags(&evURL,   cudaEventDisableTiming);
        cudaEventCreateWithFlags(&evS3,    cudaEventDisableTiming);
        cudaEventCreateWithFlags(&evFW,    cudaEventDisableTiming);
    }
};
static StreamCtx g_sc;

// ---------------- host orchestration ----------------
#define SYMADDR(p, s) do { void* _t; cudaGetSymbolAddress(&_t, s); p = (decltype(p))_t; } while (0)

extern "C" void kernel_launch(void* const* d_in, const int* in_sizes, int n_in,
                              void* d_out, int out_size) {
    const float* x_user = (const float*)d_in[0];
    const float* x_pc   = (const float*)d_in[1];
    const float* x_url  = (const float*)d_in[2];
    const int* up_src   = (const int*)d_in[3];
    const int* up_dst   = (const int*)d_in[4];
    const int* uu_src   = (const int*)d_in[5];
    const int* uu_dst   = (const int*)d_in[6];
    const float* Wu = (const float*)d_in[7];
    const float* bu = (const float*)d_in[8];
    const float* Wp = (const float*)d_in[9];
    const float* bp = (const float*)d_in[10];
    const float* Wrf = (const float*)d_in[11];
    const float* brf = (const float*)d_in[12];
    const float* Wl_pc = (const float*)d_in[13];
    const float* bl_pc = (const float*)d_in[14];
    const float* Wr_pc = (const float*)d_in[15];
    const float* Wl_url = (const float*)d_in[16];
    const float* bl_url = (const float*)d_in[17];
    const float* Wr_url = (const float*)d_in[18];
    const float* Wctx = (const float*)d_in[19];
    const float* bctx = (const float*)d_in[20];
    const float* Wc1 = (const float*)d_in[21];
    const float* bc1 = (const float*)d_in[22];
    const float* Wc2 = (const float*)d_in[23];
    const float* bc2 = (const float*)d_in[24];
    float* out = (float*)d_out;

    float *user, *pc_a, *pc_b, *url_a, *url_b, *mean_pc, *mean_url, *pcH, *urlH, *userH, *Wf, *bH;
    SYMADDR(user, g_user); SYMADDR(pc_a, g_pc_a); SYMADDR(pc_b, g_pc_b);
    SYMADDR(url_a, g_url_a); SYMADDR(url_b, g_url_b);
    SYMADDR(mean_pc, g_mean_pc); SYMADDR(mean_url, g_mean_url);
    SYMADDR(pcH, g_pcH); SYMADDR(urlH, g_urlH); SYMADDR(userH, g_userH);
    SYMADDR(Wf, g_Wf); SYMADDR(bH, g_bH);

    int *cnt_upd, *off_upd, *cur_upd, *adj_upd;
    int *cnt_uud, *off_uud, *cur_uud, *adj_uud;
    int *cnt_ups, *off_ups, *cur_ups, *adj_ups;
    int *cnt_uus, *off_uus, *cur_uus, *adj_uus;
    SYMADDR(cnt_upd, g_cnt_upd); SYMADDR(off_upd, g_off_upd); SYMADDR(cur_upd, g_cur_upd); SYMADDR(adj_upd, g_adj_upd);
    SYMADDR(cnt_uud, g_cnt_uud); SYMADDR(off_uud, g_off_uud); SYMADDR(cur_uud, g_cur_uud); SYMADDR(adj_uud, g_adj_uud);
    SYMADDR(cnt_ups, g_cnt_ups); SYMADDR(off_ups, g_off_ups); SYMADDR(cur_ups, g_cur_ups); SYMADDR(adj_ups, g_adj_ups);
    SYMADDR(cnt_uus, g_cnt_uus); SYMADDR(off_uus, g_off_uus); SYMADDR(cur_uus, g_cur_uus); SYMADDR(adj_uus, g_adj_uus);

    const int SM2 = 2 * 64 * ASTRIDE * 4;
    const int SM1 = 64 * ASTRIDE * 4;
    cudaFuncSetAttribute(gemm128, cudaFuncAttributeMaxDynamicSharedMemorySize, SM2);

    cudaStream_t s0 = 0;
    cudaStream_t s1 = g_sc.s1, s2 = g_sc.s2, s3 = g_sc.s3;

    // ---- fork ----
    cudaEventRecord(g_sc.evRoot, s0);
    cudaStreamWaitEvent(s1, g_sc.evRoot, 0);
    cudaStreamWaitEvent(s2, g_sc.evRoot, 0);
    cudaStreamWaitEvent(s3, g_sc.evRoot, 0);

    // ---- s3: weight folding (weights only), user projection, userH GEMM ----
    fuse_w_kernel<<<97, 256, 0, s3>>>(Wctx, bctx, Wc1, bc1, Wf, bH);
    cudaEventRecord(g_sc.evFW, s3);
    proj_kernel<<<(NU + 31) / 32, 128, 0, s3>>>(x_user, Wu, bu, user, NU, 6);
    cudaEventRecord(g_sc.evUser, s3);
    gemm64<<<(NU + 63) / 64, 256, SM1, s3>>>(user, Wf, bH, userH, NU);
    cudaEventRecord(g_sc.evS3, s3);

    // ---- s1/s2: pc/url input projections ----
    proj_kernel<<<(NPC + 31) / 32, 128, 0, s1>>>(x_pc, Wp, bp, pc_a, NPC, 4);
    proj_kernel<<<(NURL + 31) / 32, 128, 0, s2>>>(x_url, Wrf, brf, url_a, NURL, 3);

    // ---- s0: CSR build ----
    zero4_kernel<<<(NU + 255) / 256, 256, 0, s0>>>(cnt_upd, NPC, cnt_uud, NURL, cnt_ups, NU, cnt_uus, NU);
    count_kernel<<<(EUP + 255) / 256, 256, 0, s0>>>(up_src, up_dst, EUP, cnt_ups, cnt_upd);
    count_kernel<<<(EUU + 255) / 256, 256, 0, s0>>>(uu_src, uu_dst, EUU, cnt_uus, cnt_uud);
    SetDesc d0{cnt_upd, off_upd, cur_upd, NPC};
    SetDesc d1{cnt_uud, off_uud, cur_uud, NURL};
    SetDesc d2{cnt_ups, off_ups, cur_ups, NU};
    SetDesc d3{cnt_uus, off_uus, cur_uus, NU};
    dim3 gScan((NU + 1023) / 1024, 4);
    scanA_kernel<<<gScan, 256, 0, s0>>>(d0, d1, d2, d3);
    scanB_kernel<<<4, 128, 0, s0>>>(d0, d1, d2, d3);
    scanC_kernel<<<gScan, 256, 0, s0>>>(d0, d1, d2, d3);
    fill_kernel<<<(EUP + 255) / 256, 256, 0, s0>>>(up_src, up_dst, EUP, cur_ups, adj_ups, cur_upd, adj_upd);
    cudaEventRecord(g_sc.evCSRup, s0);
    fill_kernel<<<(EUU + 255) / 256, 256, 0, s0>>>(uu_src, uu_dst, EUU, cur_uus, adj_uus, cur_uud, adj_uud);
    cudaEventRecord(g_sc.evCSRuu, s0);

    // ---- s1: pc chain ----
    cudaStreamWaitEvent(s1, g_sc.evCSRup, 0);
    cudaStreamWaitEvent(s1, g_sc.evUser, 0);
    agg_mean_kernel<<<NPC, 128, 0, s1>>>(user, off_upd, adj_upd, mean_pc);
    gemm128<<<(NPC + 63) / 64, 256, SM2, s1>>>(mean_pc, Wl_pc, pc_a, Wr_pc, bl_pc, nullptr, pc_b, NPC, 1);
    gemm128<<<(NPC + 63) / 64, 256, SM2, s1>>>(mean_pc, Wl_pc + HD * HD, pc_b, Wr_pc + HD * HD,
                                               bl_pc + HD, pc_b, pc_a, NPC, 1);
    cudaStreamWaitEvent(s1, g_sc.evFW, 0);
    gemm64<<<(NPC + 63) / 64, 256, SM1, s1>>>(pc_a, Wf + HD * 64, nullptr, pcH, NPC);
    cudaEventRecord(g_sc.evPC, s1);

    // ---- s2: url chain ----
    cudaStreamWaitEvent(s2, g_sc.evCSRuu, 0);
    cudaStreamWaitEvent(s2, g_sc.evUser, 0);
    agg_mean_kernel<<<NURL, 128, 0, s2>>>(user, off_uud, adj_uud, mean_url);
    gemm128<<<(NURL + 63) / 64, 256, SM2, s2>>>(mean_url, Wl_url, url_a, Wr_url, bl_url, nullptr, url_b, NURL, 1);
    gemm128<<<(NURL + 63) / 64, 256, SM2, s2>>>(mean_url, Wl_url + HD * HD, url_b, Wr_url + HD * HD,
                                                bl_url + HD, url_b, url_a, NURL, 1);
    cudaStreamWaitEvent(s2, g_sc.evFW, 0);
    gemm64<<<(NURL + 63) / 64, 256, SM1, s2>>>(url_a, Wf + 2 * HD * 64, nullptr, urlH, NURL);
    cudaEventRecord(g_sc.evURL, s2);

    // ---- join on s0: fused gather + classifier ----
    cudaStreamWaitEvent(s0, g_sc.evPC, 0);
    cudaStreamWaitEvent(s0, g_sc.evURL, 0);
    cudaStreamWaitEvent(s0, g_sc.evS3, 0);
    gather_cls_kernel<<<(NU + 1) / 2, 128, 0, s0>>>(userH, pcH, urlH,
                                                    off_ups, adj_ups, off_uus, adj_uus,
                                                    Wc2, bc2, out, NU);
}

// round 6
// speedup vs baseline: 3.0435x; 1.7605x over previous
#include <cuda_runtime.h>
#include <cstdint>

#define NU   100000
#define NPC  20000
#define NURL 50000
#define EUP  250000
#define EUU  500000
#define HD   128
#define MAXB 128
#define ASTRIDE 132

// ---------------- scratch ----------------
__device__ __align__(16) float g_mx_pc[NPC*8];
__device__ __align__(16) float g_mx_url[NURL*8];
__device__ __align__(16) float g_pcH[NPC*64];
__device__ __align__(16) float g_urlH[NURL*64];

// folded weights
__device__ __align__(16) float g_Wf[3*HD*64];     // WfU | WfP | WfR  (Wctx_seg @ Wc1)
__device__ __align__(16) float g_W2pc[HD*HD];     // Wr_pc[1] + I
__device__ __align__(16) float g_W2url[HD*HD];    // Wr_url[1] + I
__device__ __align__(16) float g_A1pc[8*HD];      // [Wu;bu;0] @ Wl_pc[0]
__device__ __align__(16) float g_A2pc[8*HD];      // [Wu;bu;0] @ Wl_pc[1]
__device__ __align__(16) float g_A1url[8*HD];
__device__ __align__(16) float g_A2url[8*HD];
__device__ __align__(16) float g_B1pc[4*HD];      // Wp @ Wr_pc[0]
__device__ __align__(16) float g_c1pc[HD];        // bp @ Wr_pc[0] + bl_pc[0]
__device__ __align__(16) float g_B1url[3*HD];     // Wrf @ Wr_url[0]
__device__ __align__(16) float g_c1url[HD];
__device__ __align__(16) float g_AU[6*64];        // Wu @ WfU
__device__ __align__(16) float g_cU[64];          // bu@WfU + bctx@Wc1 + bc1

__device__ __align__(16) int g_cnt_upd[NPC];  __device__ int g_off_upd[NPC+1];  __device__ int g_cur_upd[NPC];  __device__ int g_adj_upd[EUP];
__device__ __align__(16) int g_cnt_uud[NURL]; __device__ int g_off_uud[NURL+1]; __device__ int g_cur_uud[NURL]; __device__ int g_adj_uud[EUU];
__device__ __align__(16) int g_cnt_ups[NU];   __device__ int g_off_ups[NU+1];   __device__ int g_cur_ups[NU];   __device__ int g_adj_ups[EUP];
__device__ __align__(16) int g_cnt_uus[NU];   __device__ int g_off_uus[NU+1];   __device__ int g_cur_uus[NU];   __device__ int g_adj_uus[EUU];
__device__ int g_part[4*MAXB];

// ---------------- f32x2 helpers ----------------
typedef unsigned long long u64;
__device__ __forceinline__ u64 f2fma(u64 a, u64 b, u64 c) {
    u64 d; asm("fma.rn.f32x2 %0, %1, %2, %3;" : "=l"(d) : "l"(a), "l"(b), "l"(c)); return d;
}
__device__ __forceinline__ u64 f2pack(float x) {
    u64 r; asm("mov.b64 %0, {%1, %1};" : "=l"(r) : "f"(x)); return r;
}
__device__ __forceinline__ void f2unpack(u64 v, float& x, float& y) {
    asm("mov.b64 {%0, %1}, %2;" : "=f"(x), "=f"(y) : "l"(v));
}

// ---------------- CSR build ----------------
__global__ void zero4_kernel(int* a, int na, int* b, int nb, int* c, int nc, int* d, int nd) {
    int i = blockIdx.x * blockDim.x + threadIdx.x;
    if (i < na) a[i] = 0;
    if (i < nb) b[i] = 0;
    if (i < nc) c[i] = 0;
    if (i < nd) d[i] = 0;
}

__global__ void count_kernel(const int* __restrict__ src, const int* __restrict__ dst, int E,
                             int* cntS, int* cntD) {
    int i = blockIdx.x * blockDim.x + threadIdx.x;
    if (i < E) {
        atomicAdd(&cntD[dst[i]], 1);
        atomicAdd(&cntS[src[i]], 1);
    }
}

struct SetDesc { const int* cnt; int* off; int* cur; int n; };

__device__ __forceinline__ SetDesc pick_set(int sel, SetDesc s0, SetDesc s1, SetDesc s2, SetDesc s3) {
    if (sel == 1) return s1;
    if (sel == 2) return s2;
    if (sel == 3) return s3;
    return s0;
}

__global__ void scanA_kernel(SetDesc s0, SetDesc s1, SetDesc s2, SetDesc s3) {
    SetDesc s = pick_set(blockIdx.y, s0, s1, s2, s3);
    int nb = (s.n + 1023) >> 10;
    if ((int)blockIdx.x >= nb) return;
    int tid = threadIdx.x;
    int i = blockIdx.x * 1024 + tid * 4;
    int sum = 0;
    #pragma unroll
    for (int j = 0; j < 4; j++) { int idx = i + j; if (idx < s.n) sum += s.cnt[idx]; }
    #pragma unroll
    for (int o = 16; o > 0; o >>= 1) sum += __shfl_down_sync(0xffffffffu, sum, o);
    __shared__ int ws[8];
    if ((tid & 31) == 0) ws[tid >> 5] = sum;
    __syncthreads();
    if (tid < 8) {
        int v = ws[tid];
        #pragma unroll
        for (int o = 4; o > 0; o >>= 1) v += __shfl_down_sync(0xffu, v, o);
        if (tid == 0) g_part[blockIdx.y * MAXB + blockIdx.x] = v;
    }
}

__global__ void scanB_kernel(SetDesc s0, SetDesc s1, SetDesc s2, SetDesc s3) {
    SetDesc s = pick_set(blockIdx.x, s0, s1, s2, s3);
    int nb = (s.n + 1023) >> 10;
    int tid = threadIdx.x;
    int v = (tid < nb) ? g_part[blockIdx.x * MAXB + tid] : 0;
    int lane = tid & 31, w = tid >> 5;
    int x = v;
    #pragma unroll
    for (int o = 1; o < 32; o <<= 1) { int y = __shfl_up_sync(0xffffffffu, x, o); if (lane >= o) x += y; }
    __shared__ int wt[4];
    if (lane == 31) wt[w] = x;
    __syncthreads();
    int add = 0;
    for (int j = 0; j < w; j++) add += wt[j];
    int incl = x + add;
    if (tid < nb) g_part[blockIdx.x * MAXB + tid] = incl - v;
    if (tid == 127) s.off[s.n] = incl;
}

__global__ void scanC_kernel(SetDesc s0, SetDesc s1, SetDesc s2, SetDesc s3) {
    SetDesc s = pick_set(blockIdx.y, s0, s1, s2, s3);
    int nb = (s.n + 1023) >> 10;
    if ((int)blockIdx.x >= nb) return;
    int tid = threadIdx.x;
    int base = g_part[blockIdx.y * MAXB + blockIdx.x];
    int i = blockIdx.x * 1024 + tid * 4;
    int v0 = 0, v1 = 0, v2 = 0, v3 = 0;
    if (i     < s.n) v0 = s.cnt[i];
    if (i + 1 < s.n) v1 = s.cnt[i + 1];
    if (i + 2 < s.n) v2 = s.cnt[i + 2];
    if (i + 3 < s.n) v3 = s.cnt[i + 3];
    int sv = v0 + v1 + v2 + v3;
    int lane = tid & 31, w = tid >> 5;
    int x = sv;
    #pragma unroll
    for (int o = 1; o < 32; o <<= 1) { int y = __shfl_up_sync(0xffffffffu, x, o); if (lane >= o) x += y; }
    __shared__ int wt[8];
    if (lane == 31) wt[w] = x;
    __syncthreads();
    int add = base;
    for (int j = 0; j < w; j++) add += wt[j];
    int e0 = add + x - sv;
    int e1 = e0 + v0, e2 = e1 + v1, e3 = e2 + v2;
    if (i     < s.n) { s.off[i]     = e0; s.cur[i]     = e0; }
    if (i + 1 < s.n) { s.off[i + 1] = e1; s.cur[i + 1] = e1; }
    if (i + 2 < s.n) { s.off[i + 2] = e2; s.cur[i + 2] = e2; }
    if (i + 3 < s.n) { s.off[i + 3] = e3; s.cur[i + 3] = e3; }
}

__global__ void fill_kernel(const int* __restrict__ src, const int* __restrict__ dst, int E,
                            int* curS, int* adjS, int* curD, int* adjD) {
    int i = blockIdx.x * blockDim.x + threadIdx.x;
    if (i < E) {
        int svv = src[i], dvv = dst[i];
        adjD[atomicAdd(&curD[dvv], 1)] = svv;
        adjS[atomicAdd(&curS[svv], 1)] = dvv;
    }
}

// ---------------- prep1: fold all weights ----------------
// blocks 0-95: Wf[seg] = Wctx[seg] @ Wc1 ; 96/97: W2 = Wr1 + I ;
// 98-101: A folds; 102/103: B1 + c1
__global__ void prep1_kernel(const float* __restrict__ Wctx, const float* __restrict__ Wc1,
                             const float* __restrict__ Wu, const float* __restrict__ bu,
                             const float* __restrict__ Wp, const float* __restrict__ bp,
                             const float* __restrict__ Wrf, const float* __restrict__ brf,
                             const float* __restrict__ Wl_pc, const float* __restrict__ Wr_pc,
                             const float* __restrict__ bl_pc,
                             const float* __restrict__ Wl_url, const float* __restrict__ Wr_url,
                             const float* __restrict__ bl_url,
                             float* __restrict__ Wf, float* __restrict__ W2pc, float* __restrict__ W2url,
                             float* __restrict__ A1pc, float* __restrict__ A2pc,
                             float* __restrict__ A1url, float* __restrict__ A2url,
                             float* __restrict__ B1pc, float* __restrict__ c1pc,
                             float* __restrict__ B1url, float* __restrict__ c1url)
{
    int b = blockIdx.x;
    int tid = threadIdx.x;                       // 256
    if (b < 96) {
        __shared__ float sWc1[HD * 64];
        for (int i = tid; i < HD * 64; i += 256) sWc1[i] = Wc1[i];
        __syncthreads();
        int seg = b >> 5;
        int r = (b & 31) * 4 + (tid >> 6);
        int c = tid & 63;
        int j = seg * HD + r;
        float acc = 0.f;
        #pragma unroll 8
        for (int m = 0; m < HD; m++) acc = fmaf(Wctx[j * HD + m], sWc1[m * 64 + c], acc);
        Wf[(seg * HD + r) * 64 + c] = acc;
        return;
    }
    if (b == 96 || b == 97) {
        const float* Wr1 = (b == 96) ? (Wr_pc + HD * HD) : (Wr_url + HD * HD);
        float* W2 = (b == 96) ? W2pc : W2url;
        for (int i = tid; i < HD * HD; i += 256) {
            float v = Wr1[i];
            if ((i >> 7) == (i & 127)) v += 1.f;
            W2[i] = v;
        }
        return;
    }
    if (b >= 98 && b <= 101) {
        const float* Wl;
        float* A;
        if (b == 98)      { Wl = Wl_pc;            A = A1pc; }
        else if (b == 99) { Wl = Wl_pc + HD * HD;  A = A2pc; }
        else if (b == 100){ Wl = Wl_url;           A = A1url; }
        else              { Wl = Wl_url + HD * HD; A = A2url; }
        #pragma unroll
        for (int q = 0; q < 4; q++) {
            int idx = q * 256 + tid;             // < 1024
            int r = idx >> 7, c = idx & 127;
            float acc = 0.f;
            if (r < 6) {
                #pragma unroll 8
                for (int m = 0; m < HD; m++) acc = fmaf(Wu[r * HD + m], Wl[m * HD + c], acc);
            } else if (r == 6) {
                #pragma unroll 8
                for (int m = 0; m < HD; m++) acc = fmaf(bu[m], Wl[m * HD + c], acc);
            }
            A[idx] = acc;
        }
        return;
    }
    // b == 102 / 103: B1 + c1
    {
        const float* Wsrc = (b == 102) ? Wp : Wrf;
        const float* bsrc = (b == 102) ? bp : brf;
        const float* Wr0  = (b == 102) ? Wr_pc : Wr_url;
        const float* bl0  = (b == 102) ? bl_pc : bl_url;
        float* B1 = (b == 102) ? B1pc : B1url;
        float* c1 = (b == 102) ? c1pc : c1url;
        int Kin = (b == 102) ? 4 : 3;
        int nB = Kin * HD;
        for (int idx = tid; idx < nB + HD; idx += 256) {
            if (idx < nB) {
                int r = idx / HD, c = idx % HD;
                float acc = 0.f;
                #pragma unroll 8
                for (int m = 0; m < HD; m++) acc = fmaf(Wsrc[r * HD + m], Wr0[m * HD + c], acc);
                B1[idx] = acc;
            } else {
                int c = idx - nB;
                float acc = bl0[c];
                #pragma unroll 8
                for (int m = 0; m < HD; m++) acc = fmaf(bsrc[m], Wr0[m * HD + c], acc);
                c1[c] = acc;
            }
        }
    }
}

// ---------------- prep2: AU = Wu@WfU ; cU = bu@WfU + bctx@Wc1 + bc1 ----------------
__global__ void prep2_kernel(const float* __restrict__ Wu, const float* __restrict__ bu,
                             const float* __restrict__ bctx, const float* __restrict__ Wc1,
                             const float* __restrict__ bc1, const float* __restrict__ Wf,
                             float* __restrict__ AU, float* __restrict__ cU)
{
    int c = threadIdx.x;      // 64
    for (int j = 0; j < 6; j++) {
        float acc = 0.f;
        #pragma unroll 8
        for (int m = 0; m < HD; m++) acc = fmaf(Wu[j * HD + m], Wf[m * 64 + c], acc);
        AU[j * 64 + c] = acc;
    }
    float acc = bc1[c];
    #pragma unroll 8
    for (int m = 0; m < HD; m++) acc = fmaf(bu[m], Wf[m * 64 + c], acc);
    #pragma unroll 8
    for (int m = 0; m < HD; m++) acc = fmaf(bctx[m], Wc1[m * 64 + c], acc);
    cU[c] = acc;
}

// ---------------- mx gather: mean of x_user rows (6-wide) + degree indicator ----------------
__global__ void agg_mx_kernel(const float* __restrict__ xu, const int* __restrict__ off,
                              const int* __restrict__ adj, float* __restrict__ mx, int N)
{
    int idx = blockIdx.x * 32 + (threadIdx.x >> 3);
    int j = threadIdx.x & 7;
    if (idx >= N) return;
    int beg = off[idx], end = off[idx + 1];
    if (j < 6) {
        float acc = 0.f;
        for (int e = beg; e < end; e++) acc += xu[adj[e] * 6 + j];
        float inv = (end > beg) ? 1.f / (float)(end - beg) : 0.f;
        mx[idx * 8 + j] = acc * inv;
    } else if (j == 6) {
        mx[idx * 8 + 6] = (end > beg) ? 1.f : 0.f;
    } else {
        mx[idx * 8 + 7] = 0.f;
    }
}

// ---------------- fused SAGE chain per node type ----------------
// t1 = relu(mx@A1 + xf@B1 + c1)            (K = 8 + Kin)
// t2 = relu(t1@W2 + mx@A2 + c2)            (W2 = Wr1 + I; K = 128)
// H  = t2 @ Wf64                           (K = 128 -> 64 cols)
__global__ void __launch_bounds__(256, 2) sage_fused(
    const float* __restrict__ xf, int Kin, const float* __restrict__ mx,
    const float* __restrict__ A1, const float* __restrict__ B1, const float* __restrict__ c1,
    const float* __restrict__ A2, const float* __restrict__ W2, const float* __restrict__ c2,
    const float* __restrict__ Wf64, float* __restrict__ outH, int N)
{
    extern __shared__ float smem[];
    float* T   = smem;                      // [64][ASTRIDE]
    float* U   = T + 64 * ASTRIDE;          // [64][ASTRIDE]
    float* sA1 = U + 64 * ASTRIDE;          // 8*128
    float* sA2 = sA1 + 8 * HD;              // 8*128
    float* sB1 = sA2 + 8 * HD;              // <=4*128
    float* sc1 = sB1 + 4 * HD;              // 128
    float* sc2 = sc1 + HD;                  // 128
    float* smx = sc2 + HD;                  // 64*8
    float* sxf = smx + 64 * 8;              // 64*4

    const int tid = threadIdx.x;
    const int cq = tid & 15;
    const int rg = tid >> 4;
    const int row0 = blockIdx.x * 64;

    // ---- stage ----
    #pragma unroll
    for (int q = 0; q < 4; q++) { int i = q * 256 + tid; sA1[i] = A1[i]; sA2[i] = A2[i]; }
    for (int i = tid; i < Kin * HD; i += 256) sB1[i] = B1[i];
    if (tid < HD) { sc1[tid] = c1[tid]; sc2[tid] = c2[tid]; }
    {
        int i = tid * 2;
        int gr = row0 + (i >> 3);
        float2 v = make_float2(0.f, 0.f);
        if (gr < N) v = *(const float2*)&mx[row0 * 8 + i];
        *(float2*)&smx[i] = v;
    }
    for (int i = tid; i < 64 * Kin; i += 256) {
        int r = i / Kin;
        int gr = row0 + r;
        sxf[i] = (gr < N) ? xf[row0 * Kin + i] : 0.f;
    }
    __syncthreads();

    // ---- step1: T = relu(mx@A1 + xf@B1 + c1) ----
    #pragma unroll
    for (int i = 0; i < 4; i++) {
        int r = rg + i * 16;
        float m[8];
        #pragma unroll
        for (int j = 0; j < 8; j++) m[j] = smx[r * 8 + j];
        float xr[4];
        for (int j = 0; j < Kin; j++) xr[j] = sxf[r * Kin + j];
        #pragma unroll
        for (int jj = 0; jj < 8; jj++) {
            int c = cq * 8 + jj;
            float v = sc1[c];
            #pragma unroll
            for (int j = 0; j < 8; j++) v = fmaf(m[j], sA1[j * HD + c], v);
            for (int j = 0; j < Kin; j++) v = fmaf(xr[j], sB1[j * HD + c], v);
            T[r * ASTRIDE + c] = fmaxf(v, 0.f);
        }
    }
    __syncthreads();

    // ---- step2: U = relu(T@W2 + mx@A2 + c2) ----
    {
        const ulonglong2* W2v = (const ulonglong2*)W2;
        u64 acc[4][4];
        #pragma unroll
        for (int i = 0; i < 4; i++)
            #pragma unroll
            for (int p = 0; p < 4; p++) acc[i][p] = 0ULL;
        #pragma unroll 1
        for (int k = 0; k < 128; k += 2) {
            ulonglong2 w10a = W2v[k * 32 + cq * 2];
            ulonglong2 w10b = W2v[k * 32 + cq * 2 + 1];
            ulonglong2 w11a = W2v[(k + 1) * 32 + cq * 2];
            ulonglong2 w11b = W2v[(k + 1) * 32 + cq * 2 + 1];
            #pragma unroll
            for (int i = 0; i < 4; i++) {
                float2 a2 = *(const float2*)&T[(rg + i * 16) * ASTRIDE + k];
                u64 aa0 = f2pack(a2.x), aa1 = f2pack(a2.y);
                acc[i][0] = f2fma(aa0, w10a.x, acc[i][0]);
                acc[i][1] = f2fma(aa0, w10a.y, acc[i][1]);
                acc[i][2] = f2fma(aa0, w10b.x, acc[i][2]);
                acc[i][3] = f2fma(aa0, w10b.y, acc[i][3]);
                acc[i][0] = f2fma(aa1, w11a.x, acc[i][0]);
                acc[i][1] = f2fma(aa1, w11a.y, acc[i][1]);
                acc[i][2] = f2fma(aa1, w11b.x, acc[i][2]);
                acc[i][3] = f2fma(aa1, w11b.y, acc[i][3]);
            }
        }
        #pragma unroll
        for (int i = 0; i < 4; i++) {
            int r = rg + i * 16;
            float o[8];
            f2unpack(acc[i][0], o[0], o[1]);
            f2unpack(acc[i][1], o[2], o[3]);
            f2unpack(acc[i][2], o[4], o[5]);
            f2unpack(acc[i][3], o[6], o[7]);
            float m[8];
            #pragma unroll
            for (int j = 0; j < 8; j++) m[j] = smx[r * 8 + j];
            #pragma unroll
            for (int jj = 0; jj < 8; jj++) {
                int c = cq * 8 + jj;
                float v = o[jj] + sc2[c];
                #pragma unroll
                for (int j = 0; j < 8; j++) v = fmaf(m[j], sA2[j * HD + c], v);
                U[r * ASTRIDE + c] = fmaxf(v, 0.f);
            }
        }
    }
    __syncthreads();

    // ---- step3: outH = U @ Wf64 ----
    {
        const ulonglong2* Wv = (const ulonglong2*)Wf64;
        u64 acc[4][2];
        #pragma unroll
        for (int i = 0; i < 4; i++) { acc[i][0] = 0ULL; acc[i][1] = 0ULL; }
        #pragma unroll 2
        for (int k = 0; k < 128; k += 2) {
            ulonglong2 wA = Wv[k * 16 + cq];
            ulonglong2 wB = Wv[(k + 1) * 16 + cq];
            #pragma unroll
            for (int i = 0; i < 4; i++) {
                float2 a2 = *(const float2*)&U[(rg + i * 16) * ASTRIDE + k];
                u64 aa0 = f2pack(a2.x), aa1 = f2pack(a2.y);
                acc[i][0] = f2fma(aa0, wA.x, acc[i][0]);
                acc[i][1] = f2fma(aa0, wA.y, acc[i][1]);
                acc[i][0] = f2fma(aa1, wB.x, acc[i][0]);
                acc[i][1] = f2fma(aa1, wB.y, acc[i][1]);
            }
        }
        const int c0 = cq * 4;
        #pragma unroll
        for (int i = 0; i < 4; i++) {
            int gr = row0 + rg + i * 16;
            if (gr >= N) continue;
            float o[4];
            f2unpack(acc[i][0], o[0], o[1]);
            f2unpack(acc[i][1], o[2], o[3]);
            *(float4*)(outH + gr * 64 + c0) = make_float4(o[0], o[1], o[2], o[3]);
        }
    }
}

// ---------------- fused gather + user-term + classifier ----------------
// out[u] = relu(x_user[u]@AU + cU + sum pcH[dst] + sum urlH[dst]) @ Wc2 + bc2
__global__ void __launch_bounds__(256) gather_cls_kernel(
    const float* __restrict__ xu, const float* __restrict__ AU, const float* __restrict__ cU,
    const float* __restrict__ pcH, const float* __restrict__ urlH,
    const int* __restrict__ offP, const int* __restrict__ adjP,
    const int* __restrict__ offR, const int* __restrict__ adjR,
    const float* __restrict__ Wc2, const float* __restrict__ bc2,
    float* __restrict__ out, int N)
{
    __shared__ float sAU[6 * 64];
    __shared__ float sW2[128];
    __shared__ float scU[64];
    __shared__ float sx[4][6];
    __shared__ float red[8][2];
    int tid = threadIdx.x;                    // 256 = 4 users x 64
    for (int i = tid; i < 384; i += 256) sAU[i] = AU[i];
    if (tid < 128) sW2[tid] = Wc2[tid];
    if (tid >= 128 && tid < 192) scU[tid - 128] = cU[tid - 128];
    if (tid >= 192 && tid < 216) {
        int ul = (tid - 192) / 6, j = (tid - 192) % 6;
        int uu = blockIdx.x * 4 + ul;
        sx[ul][j] = (uu < N) ? xu[uu * 6 + j] : 0.f;
    }
    __syncthreads();

    int ul = tid >> 6;
    int u = blockIdx.x * 4 + ul;
    int t = tid & 63;
    float acc = scU[t];
    #pragma unroll
    for (int j = 0; j < 6; j++) acc = fmaf(sx[ul][j], sAU[j * 64 + t], acc);
    if (u < N) {
        {
            int e = offP[u], end = offP[u + 1];
            for (; e + 4 <= end; e += 4) {
                int i0 = adjP[e], i1 = adjP[e+1], i2 = adjP[e+2], i3 = adjP[e+3];
                acc += (pcH[i0 * 64 + t] + pcH[i1 * 64 + t]) + (pcH[i2 * 64 + t] + pcH[i3 * 64 + t]);
            }
            for (; e < end; e++) acc += pcH[adjP[e] * 64 + t];
        }
        {
            int e = offR[u], end = offR[u + 1];
            for (; e + 4 <= end; e += 4) {
                int i0 = adjR[e], i1 = adjR[e+1], i2 = adjR[e+2], i3 = adjR[e+3];
                acc += (urlH[i0 * 64 + t] + urlH[i1 * 64 + t]) + (urlH[i2 * 64 + t] + urlH[i3 * 64 + t]);
            }
            for (; e < end; e++) acc += urlH[adjR[e] * 64 + t];
        }
    }
    float h = fmaxf(acc, 0.f);
    float p0 = h * sW2[t * 2 + 0];
    float p1 = h * sW2[t * 2 + 1];
    #pragma unroll
    for (int o = 16; o > 0; o >>= 1) {
        p0 += __shfl_down_sync(0xffffffffu, p0, o);
        p1 += __shfl_down_sync(0xffffffffu, p1, o);
    }
    int w = tid >> 5;
    if ((tid & 31) == 0) { red[w][0] = p0; red[w][1] = p1; }
    __syncthreads();
    if (tid < 8) {
        int uw = tid >> 1, c = tid & 1;
        int uu = blockIdx.x * 4 + uw;
        if (uu < N) out[uu * 2 + c] = red[uw * 2][c] + red[uw * 2 + 1][c] + bc2[c];
    }
}

// ---------------- streams/events (static init) ----------------
struct StreamCtx {
    cudaStream_t s1, s2, s3;
    cudaEvent_t evRoot, evCSRup, evCSRuu, evPrep, evPC, evURL;
    StreamCtx() {
        cudaStreamCreateWithFlags(&s1, cudaStreamNonBlocking);
        cudaStreamCreateWithFlags(&s2, cudaStreamNonBlocking);
        cudaStreamCreateWithFlags(&s3, cudaStreamNonBlocking);
        cudaEventCreateWithFlags(&evRoot,  cudaEventDisableTiming);
        cudaEventCreateWithFlags(&evCSRup, cudaEventDisableTiming);
        cudaEventCreateWithFlags(&evCSRuu, cudaEventDisableTiming);
        cudaEventCreateWithFlags(&evPrep,  cudaEventDisableTiming);
        cudaEventCreateWithFlags(&evPC,    cudaEventDisableTiming);
        cudaEventCreateWithFlags(&evURL,   cudaEventDisableTiming);
    }
};
static StreamCtx g_sc;

// ---------------- host orchestration ----------------
#define SYMADDR(p, s) do { void* _t; cudaGetSymbolAddress(&_t, s); p = (decltype(p))_t; } while (0)

extern "C" void kernel_launch(void* const* d_in, const int* in_sizes, int n_in,
                              void* d_out, int out_size) {
    const float* x_user = (const float*)d_in[0];
    const float* x_pc   = (const float*)d_in[1];
    const float* x_url  = (const float*)d_in[2];
    const int* up_src   = (const int*)d_in[3];
    const int* up_dst   = (const int*)d_in[4];
    const int* uu_src   = (const int*)d_in[5];
    const int* uu_dst   = (const int*)d_in[6];
    const float* Wu = (const float*)d_in[7];
    const float* bu = (const float*)d_in[8];
    const float* Wp = (const float*)d_in[9];
    const float* bp = (const float*)d_in[10];
    const float* Wrf = (const float*)d_in[11];
    const float* brf = (const float*)d_in[12];
    const float* Wl_pc = (const float*)d_in[13];
    const float* bl_pc = (const float*)d_in[14];
    const float* Wr_pc = (const float*)d_in[15];
    const float* Wl_url = (const float*)d_in[16];
    const float* bl_url = (const float*)d_in[17];
    const float* Wr_url = (const float*)d_in[18];
    const float* Wctx = (const float*)d_in[19];
    const float* bctx = (const float*)d_in[20];
    const float* Wc1 = (const float*)d_in[21];
    const float* bc1 = (const float*)d_in[22];
    const float* Wc2 = (const float*)d_in[23];
    const float* bc2 = (const float*)d_in[24];
    float* out = (float*)d_out;

    float *mx_pc, *mx_url, *pcH, *urlH;
    float *Wf, *W2pc, *W2url, *A1pc, *A2pc, *A1url, *A2url, *B1pc, *c1pc, *B1url, *c1url, *AU, *cU;
    SYMADDR(mx_pc, g_mx_pc); SYMADDR(mx_url, g_mx_url);
    SYMADDR(pcH, g_pcH); SYMADDR(urlH, g_urlH);
    SYMADDR(Wf, g_Wf); SYMADDR(W2pc, g_W2pc); SYMADDR(W2url, g_W2url);
    SYMADDR(A1pc, g_A1pc); SYMADDR(A2pc, g_A2pc); SYMADDR(A1url, g_A1url); SYMADDR(A2url, g_A2url);
    SYMADDR(B1pc, g_B1pc); SYMADDR(c1pc, g_c1pc); SYMADDR(B1url, g_B1url); SYMADDR(c1url, g_c1url);
    SYMADDR(AU, g_AU); SYMADDR(cU, g_cU);

    int *cnt_upd, *off_upd, *cur_upd, *adj_upd;
    int *cnt_uud, *off_uud, *cur_uud, *adj_uud;
    int *cnt_ups, *off_ups, *cur_ups, *adj_ups;
    int *cnt_uus, *off_uus, *cur_uus, *adj_uus;
    SYMADDR(cnt_upd, g_cnt_upd); SYMADDR(off_upd, g_off_upd); SYMADDR(cur_upd, g_cur_upd); SYMADDR(adj_upd, g_adj_upd);
    SYMADDR(cnt_uud, g_cnt_uud); SYMADDR(off_uud, g_off_uud); SYMADDR(cur_uud, g_cur_uud); SYMADDR(adj_uud, g_adj_uud);
    SYMADDR(cnt_ups, g_cnt_ups); SYMADDR(off_ups, g_off_ups); SYMADDR(cur_ups, g_cur_ups); SYMADDR(adj_ups, g_adj_ups);
    SYMADDR(cnt_uus, g_cnt_uus); SYMADDR(off_uus, g_off_uus); SYMADDR(cur_uus, g_cur_uus); SYMADDR(adj_uus, g_adj_uus);

    const int SAGE_SMEM = (2 * 64 * ASTRIDE + 8 * HD * 2 + 4 * HD + 2 * HD + 64 * 8 + 64 * 4) * 4;
    cudaFuncSetAttribute(sage_fused, cudaFuncAttributeMaxDynamicSharedMemorySize, SAGE_SMEM);

    cudaStream_t s0 = 0;
    cudaStream_t s1 = g_sc.s1, s2 = g_sc.s2, s3 = g_sc.s3;

    // ---- fork ----
    cudaEventRecord(g_sc.evRoot, s0);
    cudaStreamWaitEvent(s1, g_sc.evRoot, 0);
    cudaStreamWaitEvent(s2, g_sc.evRoot, 0);
    cudaStreamWaitEvent(s3, g_sc.evRoot, 0);

    // ---- s3: weight folding ----
    prep1_kernel<<<104, 256, 0, s3>>>(Wctx, Wc1, Wu, bu, Wp, bp, Wrf, brf,
                                      Wl_pc, Wr_pc, bl_pc, Wl_url, Wr_url, bl_url,
                                      Wf, W2pc, W2url, A1pc, A2pc, A1url, A2url,
                                      B1pc, c1pc, B1url, c1url);
    prep2_kernel<<<1, 64, 0, s3>>>(Wu, bu, bctx, Wc1, bc1, Wf, AU, cU);
    cudaEventRecord(g_sc.evPrep, s3);

    // ---- s0: CSR build (url first — longest chain) ----
    zero4_kernel<<<(NU + 255) / 256, 256, 0, s0>>>(cnt_upd, NPC, cnt_uud, NURL, cnt_ups, NU, cnt_uus, NU);
    count_kernel<<<(EUU + 255) / 256, 256, 0, s0>>>(uu_src, uu_dst, EUU, cnt_uus, cnt_uud);
    count_kernel<<<(EUP + 255) / 256, 256, 0, s0>>>(up_src, up_dst, EUP, cnt_ups, cnt_upd);
    SetDesc d0{cnt_upd, off_upd, cur_upd, NPC};
    SetDesc d1{cnt_uud, off_uud, cur_uud, NURL};
    SetDesc d2{cnt_ups, off_ups, cur_ups, NU};
    SetDesc d3{cnt_uus, off_uus, cur_uus, NU};
    dim3 gScan((NU + 1023) / 1024, 4);
    scanA_kernel<<<gScan, 256, 0, s0>>>(d0, d1, d2, d3);
    scanB_kernel<<<4, 128, 0, s0>>>(d0, d1, d2, d3);
    scanC_kernel<<<gScan, 256, 0, s0>>>(d0, d1, d2, d3);
    fill_kernel<<<(EUU + 255) / 256, 256, 0, s0>>>(uu_src, uu_dst, EUU, cur_uus, adj_uus, cur_uud, adj_uud);
    cudaEventRecord(g_sc.evCSRuu, s0);
    fill_kernel<<<(EUP + 255) / 256, 256, 0, s0>>>(up_src, up_dst, EUP, cur_ups, adj_ups, cur_upd, adj_upd);
    cudaEventRecord(g_sc.evCSRup, s0);

    // ---- s2: url chain ----
    cudaStreamWaitEvent(s2, g_sc.evCSRuu, 0);
    cudaStreamWaitEvent(s2, g_sc.evPrep, 0);
    agg_mx_kernel<<<(NURL + 31) / 32, 256, 0, s2>>>(x_user, off_uud, adj_uud, mx_url, NURL);
    sage_fused<<<(NURL + 63) / 64, 256, SAGE_SMEM, s2>>>(x_url, 3, mx_url,
                                                         A1url, B1url, c1url,
                                                         A2url, W2url, bl_url + HD,
                                                         Wf + 2 * HD * 64, urlH, NURL);
    cudaEventRecord(g_sc.evURL, s2);

    // ---- s1: pc chain ----
    cudaStreamWaitEvent(s1, g_sc.evCSRup, 0);
    cudaStreamWaitEvent(s1, g_sc.evPrep, 0);
    agg_mx_kernel<<<(NPC + 31) / 32, 256, 0, s1>>>(x_user, off_upd, adj_upd, mx_pc, NPC);
    sage_fused<<<(NPC + 63) / 64, 256, SAGE_SMEM, s1>>>(x_pc, 4, mx_pc,
                                                        A1pc, B1pc, c1pc,
                                                        A2pc, W2pc, bl_pc + HD,
                                                        Wf + HD * 64, pcH, NPC);
    cudaEventRecord(g_sc.evPC, s1);

    // ---- join on s0: fused gather + classifier ----
    cudaStreamWaitEvent(s0, g_sc.evPC, 0);
    cudaStreamWaitEvent(s0, g_sc.evURL, 0);
    gather_cls_kernel<<<(NU + 3) / 4, 256, 0, s0>>>(x_user, AU, cU, pcH, urlH,
                                                    off_ups, adj_ups, off_uus, adj_uus,
                                                    Wc2, bc2, out, NU);
}